// round 16
// baseline (speedup 1.0000x reference)
#include <cuda_runtime.h>
#include <cuda_fp16.h>
#include <cstdint>
#include <math.h>

typedef unsigned long long ull;
typedef unsigned int u32;

#define NN 512
#define DD 64
#define BB 8
#define KSEL 256
#define G 8                   // i-values per CTA in k1

// Scratch (no allocation allowed)
__device__ float g_L[(size_t)BB * NN * NN];   // logits  8 MB
__device__ float g_h[(size_t)BB * NN * DD];   // h after selu
__device__ float g_s[(size_t)BB * NN];        // sigmoid scores
__device__ __half2 g_xhi[(size_t)BB * NN * 32];  // fp16 hi of x
__device__ __half2 g_xlo[(size_t)BB * NN * 32];  // fp16 lo residual

// Fast tanh: ex2.approx + rcp.approx + 1 Newton step. abs err ~1e-7.
__device__ __forceinline__ float fast_tanh(float x) {
    float ax = fabsf(x), t, r;
    asm("ex2.approx.f32 %0, %1;" : "=f"(t) : "f"(ax * -2.8853900817779268f));
    float u = 1.0f + t;
    asm("rcp.approx.f32 %0, %1;" : "=f"(r) : "f"(u));
    r = r * fmaf(-u, r, 2.0f);
    return copysignf((1.0f - t) * r, x);
}

__device__ __forceinline__ u32 smem_u32(const void* p) {
    u32 a;
    asm("{ .reg .u64 t; cvta.to.shared.u64 t, %1; cvt.u32.u64 %0, t; }" : "=r"(a) : "l"(p));
    return a;
}

#define LDSM4(r0, r1, r2, r3, a) \
    asm volatile("ldmatrix.sync.aligned.m8n8.x4.shared.b16 {%0,%1,%2,%3}, [%4];" \
        : "=r"(r0), "=r"(r1), "=r"(r2), "=r"(r3) : "r"(a))

__device__ __forceinline__ void mma16816(float* c, const u32* a, u32 b0, u32 b1) {
    asm volatile(
        "mma.sync.aligned.m16n8k16.row.col.f32.f16.f16.f32 "
        "{%0,%1,%2,%3}, {%4,%5,%6,%7}, {%8,%9}, {%0,%1,%2,%3};"
        : "+f"(c[0]), "+f"(c[1]), "+f"(c[2]), "+f"(c[3])
        : "r"(a[0]), "r"(a[1]), "r"(a[2]), "r"(a[3]), "r"(b0), "r"(b1));
}

// ---------------- Kernel 0: convert x to fp16 hi/lo (once) ----------------
__global__ __launch_bounds__(256) void k0_cvt(const float* __restrict__ x)
{
    int t = blockIdx.x * 256 + threadIdx.x;   // over 131072 float2
    float2 v = ((const float2*)x)[t];
    __half h0 = __float2half_rn(v.x), h1 = __float2half_rn(v.y);
    __half l0 = __float2half_rn(v.x - __half2float(h0));
    __half l1 = __float2half_rn(v.y - __half2float(h1));
    g_xhi[t] = __halves2half2(h0, h1);
    g_xlo[t] = __halves2half2(l0, l1);
}

// ---------------- Kernel 1: logits via HMMA fp16 hi/lo ---------------------
// Full-256-j CTAs, 32 j-rows per warp (2 m16 tiles), G=8 i per CTA.
// Swizzled 128B rows, single-buffer B, 2 syncs per g.
#define RWIN  264            // window rows: 256 + G
#define ATILE (RWIN * 128)   // 33792
#define BTILE (64 * 128)     // 8192
#define OFF_XI  0            // G*64 floats = 2048 B
#define OFF_VV  2048
#define OFF_BV  2304
#define OFF_RED 2560
#define OFF_AHI 3072
#define OFF_ALO (OFF_AHI + ATILE)
#define OFF_BHI (OFF_ALO + ATILE)
#define OFF_BLO (OFF_BHI + BTILE)
#define SMEM1   (OFF_BLO + BTILE)            // 87040 bytes -> 2 CTAs/SM

// swizzle: 16B chunk c (0..7) of row r stored at chunk (c ^ (r&7))
#define SWZ(r, c) ((u32)((r) * 128 + ((((c) ^ ((r) & 7))) << 4)))

__global__ __launch_bounds__(256, 2) void k1_logits(
    const float* __restrict__ x, const float* __restrict__ attw,
    const float* __restrict__ attb, const float* __restrict__ attv)
{
    extern __shared__ char smem[];
    const u32 sb = smem_u32(smem);
    const int tid = threadIdx.x, w = tid >> 5, lane = tid & 31;
    const int i0 = blockIdx.x * G, b = blockIdx.y;

    float* xia = (float*)(smem + OFF_XI);     // [G][64]
    float* vv  = (float*)(smem + OFF_VV);
    float* bv  = (float*)(smem + OFF_BV);
    float* red = (float*)(smem + OFF_RED);

    const float* xb = x + (size_t)b * NN * DD;

    if (tid < 64) { vv[tid] = attv[tid]; bv[tid] = attb[tid]; }
    xia[tid]       = xb[(size_t)i0 * DD + tid];        // rows i0..i0+7
    xia[tid + 256] = xb[(size_t)i0 * DD + tid + 256];

    // A fill: fp16 hi/lo rows for j-offsets [0, 263], swizzled
    {
        const float4* xh4 = (const float4*)g_xhi;
        const float4* xl4 = (const float4*)g_xlo;
        for (int idx = tid; idx < RWIN * 8; idx += 256) {
            int r = idx >> 3, c = idx & 7;
            int grow = (i0 + r) & (NN - 1);
            size_t src = (size_t)(b * NN + grow) * 8 + c;
            u32 dst = SWZ(r, c);
            *(float4*)(smem + OFF_AHI + dst) = xh4[src];
            *(float4*)(smem + OFF_ALO + dst) = xl4[src];
        }
    }

    // B fill: B[o][d] = x_i[d]*W[d][o], fp16 hi/lo, swizzled, paired stores
    auto fillB = [&](int g) {
        char* bhi = smem + OFF_BHI;
        char* blo = smem + OFF_BLO;
        const float* xg = xia + g * 64;
        #pragma unroll
        for (int k = 0; k < 8; k++) {      // 64 o x 32 d-pairs / 256 threads
            int idx = tid + k * 256;
            int dp = idx >> 6, o = idx & 63;
            float w0 = xg[2 * dp]     * attw[(2 * dp)     * 64 + o];
            float w1 = xg[2 * dp + 1] * attw[(2 * dp + 1) * 64 + o];
            __half h0 = __float2half_rn(w0), h1 = __float2half_rn(w1);
            __half l0 = __float2half_rn(w0 - __half2float(h0));
            __half l1 = __float2half_rn(w1 - __half2float(h1));
            u32 off = SWZ(o, dp >> 2) + (u32)((dp & 3) * 4);
            *(__half2*)(bhi + off) = __halves2half2(h0, h1);
            *(__half2*)(blo + off) = __halves2half2(l0, l1);
        }
    };

    // lane decomposition for ldmatrix addressing
    const int la15 = lane & 15;
    const u32 la7  = (u32)(lane & 7);
    const u32 ak8  = (u32)((lane >> 4) & 1);   // A k-chunk select
    const u32 bk8  = (u32)((lane >> 3) & 1);   // B k-chunk select
    const u32 bhi8 = (u32)(((lane >> 4) & 1) * 8);

    for (int g = 0; g < G; g++) {
        const int i = i0 + g;
        __syncthreads();   // prologue (g=0) / prior-g B reads done
        fillB(g);
        __syncthreads();   // B visible

        const int rA = w * 32 + la15 + g;      // (rA+16)&7 == rA&7
        const u32 r7a = (u32)(rA & 7);
        const u32 aHiRow = sb + OFF_AHI + (u32)(rA * 128);
        const u32 aLoRow = aHiRow + ATILE;
        const u32 bB = sb + OFF_BHI;

        float acc[2][8][4];
        #pragma unroll
        for (int mt = 0; mt < 2; mt++)
            #pragma unroll
            for (int nt = 0; nt < 8; nt++)
                #pragma unroll
                for (int q = 0; q < 4; q++) acc[mt][nt][q] = 0.f;

        #pragma unroll
        for (int ks = 0; ks < 4; ks++) {
            const u32 aswz = (u32)((((u32)(2 * ks) + ak8) ^ r7a) << 4);
            const u32 bswz = (u32)((((u32)(2 * ks) + bk8) ^ la7) << 4);
            u32 ah[2][4], bh[8][2];
            LDSM4(ah[0][0], ah[0][1], ah[0][2], ah[0][3], aHiRow + aswz);
            LDSM4(ah[1][0], ah[1][1], ah[1][2], ah[1][3], aHiRow + 16 * 128 + aswz);
            #pragma unroll
            for (int q = 0; q < 4; q++) {
                u32 brow = bB + (u32)((q * 16 + bhi8 + la7) * 128) + bswz;
                LDSM4(bh[2 * q][0], bh[2 * q][1], bh[2 * q + 1][0], bh[2 * q + 1][1], brow);
            }
            #pragma unroll
            for (int mt = 0; mt < 2; mt++)
                #pragma unroll
                for (int nt = 0; nt < 8; nt++)
                    mma16816(acc[mt][nt], ah[mt], bh[nt][0], bh[nt][1]);
            {
                u32 bl[8][2];
                #pragma unroll
                for (int q = 0; q < 4; q++) {
                    u32 brow = bB + BTILE + (u32)((q * 16 + bhi8 + la7) * 128) + bswz;
                    LDSM4(bl[2 * q][0], bl[2 * q][1], bl[2 * q + 1][0], bl[2 * q + 1][1], brow);
                }
                #pragma unroll
                for (int mt = 0; mt < 2; mt++)
                    #pragma unroll
                    for (int nt = 0; nt < 8; nt++)
                        mma16816(acc[mt][nt], ah[mt], bl[nt][0], bl[nt][1]);
            }
            {
                u32 al[2][4];
                LDSM4(al[0][0], al[0][1], al[0][2], al[0][3], aLoRow + aswz);
                LDSM4(al[1][0], al[1][1], al[1][2], al[1][3], aLoRow + 16 * 128 + aswz);
                #pragma unroll
                for (int mt = 0; mt < 2; mt++)
                    #pragma unroll
                    for (int nt = 0; nt < 8; nt++)
                        mma16816(acc[mt][nt], al[mt], bh[nt][0], bh[nt][1]);
            }
        }

        // Epilogue: tanh + v-weighted o-reduction; lanes share j across c=lane&3
        {
            const int gq = lane >> 2, c = lane & 3;
            float2 vv2[8], bv2[8];
            #pragma unroll
            for (int nt = 0; nt < 8; nt++) {
                vv2[nt] = *(const float2*)&vv[nt * 8 + 2 * c];
                bv2[nt] = *(const float2*)&bv[nt * 8 + 2 * c];
            }
            #pragma unroll
            for (int mt = 0; mt < 2; mt++) {
                #pragma unroll
                for (int rh = 0; rh < 2; rh++) {
                    float s = 0.f;
                    #pragma unroll
                    for (int nt = 0; nt < 8; nt++) {
                        s += vv2[nt].x * fast_tanh(acc[mt][nt][2 * rh]     + bv2[nt].x);
                        s += vv2[nt].y * fast_tanh(acc[mt][nt][2 * rh + 1] + bv2[nt].y);
                    }
                    s += __shfl_xor_sync(~0u, s, 1);
                    s += __shfl_xor_sync(~0u, s, 2);
                    if (c == 0) {
                        int jloc = w * 32 + mt * 16 + rh * 8 + gq;
                        int jg = (i + jloc) & (NN - 1);
                        g_L[((size_t)b * NN + i) * NN + jg] = s;
                        g_L[((size_t)b * NN + jg) * NN + i] = s;  // mirror
                    }
                }
            }
        }
    }

    // Tail k=256: CTAs with i0<256; 8 i's in two half-passes
    if (i0 < 256) {
        __syncthreads();
        const int o = tid & 63;
        #pragma unroll
        for (int half = 0; half < 2; half++) {
            const int g = (tid >> 6) + half * 4;
            const float* xg = xia + g * 64;
            const float* xj = xb + (size_t)(i0 + g + 256) * DD;
            float q2 = bv[o];
            #pragma unroll 8
            for (int d = 0; d < 64; d++)
                q2 = fmaf(xg[d] * attw[d * 64 + o], xj[d], q2);
            float s = vv[o] * fast_tanh(q2);
            #pragma unroll
            for (int off = 16; off; off >>= 1) s += __shfl_xor_sync(~0u, s, off);
            if (lane == 0) red[half * 8 + w] = s;   // warp w covers g=(w>>1)+4*half
        }
        __syncthreads();
        if (tid < G) {
            int hf = tid >> 2, gl = tid & 3;
            float sv = red[hf * 8 + 2 * gl] + red[hf * 8 + 2 * gl + 1];
            int ii = i0 + tid, jg = ii + 256;
            g_L[((size_t)b * NN + ii) * NN + jg] = sv;
            g_L[((size_t)b * NN + jg) * NN + ii] = sv;
        }
    }
}

// ---------------------------------------------------------------------------
// Kernel 2 (tiled, 1024 threads): j-split agg halves the per-CTA critical path.
// ---------------------------------------------------------------------------
#define ITILE 32
__global__ __launch_bounds__(1024, 1) void k2_head(
    const float* __restrict__ x,
    const float* __restrict__ pwa_w, const float* __restrict__ pwa_b,
    const float* __restrict__ pwo_w, const float* __restrict__ pwo_b,
    const float* __restrict__ gamma, const float* __restrict__ beta,
    const float* __restrict__ poolw, const float* __restrict__ poolb)
{
    extern __shared__ float s2[];
    float* att  = s2;                        // [32][512] (reused as hsm later)
    float* xs   = s2 + ITILE * NN;           // [512][64]
    float* agg  = xs + NN * DD;              // [32][64]
    float* aggp = agg + ITILE * DD;          // [2][32][64]
    float* inv  = aggp + 2 * ITILE * DD;     // [32]
    float* hsm  = att;

    const int itile = blockIdx.x, b = blockIdx.y;
    const int tid = threadIdx.x;
    const int wid = tid >> 5, lane = tid & 31;

    {
        const float4* Ls = (const float4*)(g_L + ((size_t)b * NN + itile * ITILE) * NN);
        float4* Ld = (float4*)att;
        for (int idx = tid; idx < ITILE * NN / 4; idx += 1024) Ld[idx] = Ls[idx];
        const float4* Xs = (const float4*)(x + (size_t)b * NN * DD);
        float4* Xd = (float4*)xs;
        for (int idx = tid; idx < NN * DD / 4; idx += 1024) Xd[idx] = Xs[idx];
    }
    __syncthreads();

    // Row softmax: 32 warps, 1 row each; exp in place (unnormalized), 1/sum
    {
        int r = wid;
        float* row = att + r * NN;
        float m = -1e30f;
        #pragma unroll 4
        for (int j = lane; j < NN; j += 32) m = fmaxf(m, row[j]);
        #pragma unroll
        for (int off = 16; off; off >>= 1) m = fmaxf(m, __shfl_xor_sync(~0u, m, off));
        float ssum = 0.f;
        #pragma unroll 4
        for (int j = lane; j < NN; j += 32) {
            float e = __expf(row[j] - m);
            row[j] = e;
            ssum += e;
        }
        #pragma unroll
        for (int off = 16; off; off >>= 1) ssum += __shfl_xor_sync(~0u, ssum, off);
        if (lane == 0) inv[r] = 1.0f / ssum;
    }
    __syncthreads();

    // agg partials: (seg, ig, d): rows ig*4..+3, j in [seg*256, seg*256+256)
    {
        const int d = tid & 63, ig = (tid >> 6) & 7, seg = tid >> 9;
        float acc[4] = {0, 0, 0, 0};
        for (int j = seg * 256; j < seg * 256 + 256; j += 4) {
            float x0 = xs[(j + 0) * DD + d];
            float x1 = xs[(j + 1) * DD + d];
            float x2 = xs[(j + 2) * DD + d];
            float x3 = xs[(j + 3) * DD + d];
            #pragma unroll
            for (int s = 0; s < 4; s++) {
                float4 a = *(const float4*)&att[(ig * 4 + s) * NN + j];
                acc[s] = fmaf(a.x, x0, acc[s]);
                acc[s] = fmaf(a.y, x1, acc[s]);
                acc[s] = fmaf(a.z, x2, acc[s]);
                acc[s] = fmaf(a.w, x3, acc[s]);
            }
        }
        #pragma unroll
        for (int s = 0; s < 4; s++)
            aggp[(seg * ITILE + ig * 4 + s) * DD + d] = acc[s];
    }
    __syncthreads();
    for (int t = tid; t < ITILE * DD; t += 1024)
        agg[t] = (aggp[t] + aggp[ITILE * DD + t]) * inv[t >> 6];
    __syncthreads();

    // h = agg@pwa + x_i@pwo + biases, BN(eval) scale, selu; 2 rows/thread
    {
        const int o = tid & 63, ig2 = tid >> 6;   // ig2 in 0..15
        float hv[2];
        float pb = pwa_b[o] + pwo_b[o];
        hv[0] = pb; hv[1] = pb;
        #pragma unroll 8
        for (int dd = 0; dd < 64; dd++) {
            float wa = __ldg(&pwa_w[dd * 64 + o]);
            float wo = __ldg(&pwo_w[dd * 64 + o]);
            #pragma unroll
            for (int s = 0; s < 2; s++) {
                int ii = ig2 * 2 + s;
                hv[s] = fmaf(agg[ii * DD + dd], wa, hv[s]);
                hv[s] = fmaf(xs[(itile * ITILE + ii) * DD + dd], wo, hv[s]);
            }
        }
        const float BNS = 0.99999500003749969f;
        float gam = gamma[o] * BNS, bet = beta[o];
        const float SC = 1.0507009873554804934193349852946f;
        const float AL = 1.6732632423543772848170429916717f;
        #pragma unroll
        for (int s = 0; s < 2; s++) {
            float h = fmaf(hv[s], gam, bet);
            h = h > 0.f ? SC * h : SC * AL * expm1f(h);
            hsm[(ig2 * 2 + s) * DD + o] = h;
        }
    }
    __syncthreads();

    if (tid < ITILE) {
        float z = poolb[0];
        #pragma unroll 8
        for (int oo = 0; oo < 64; oo++) z = fmaf(hsm[tid * 64 + oo], poolw[oo], z);
        g_s[(size_t)b * NN + itile * ITILE + tid] = 1.0f / (1.0f + expf(-z));
    }
    {
        float4* gh = (float4*)(g_h + ((size_t)b * NN + itile * ITILE) * DD);
        const float4* hs = (const float4*)hsm;
        for (int idx = tid; idx < ITILE * DD / 4; idx += 1024) gh[idx] = hs[idx];
    }
}

// ---------------------------------------------------------------------------
// Kernel 3: split-scan rank top-256 (unchanged proven version).
// ---------------------------------------------------------------------------
__global__ __launch_bounds__(512) void k3_topk(float* __restrict__ out)
{
    __shared__ ull keys[NN];
    __shared__ int pr[4][128];
    __shared__ int rankS[128];
    __shared__ float scS[128];
    const int b = blockIdx.x, qd = blockIdx.y, tid = threadIdx.x;

    {
        float sc = g_s[(size_t)b * NN + tid];
        keys[tid] = ((ull)__float_as_uint(sc) << 32) | (ull)(unsigned)(511 - tid);
    }
    __syncthreads();

    const int sub = tid >> 7, el = tid & 127;
    const int e = qd * 128 + el;
    const ull mykey = keys[e];
    int part = 0;
    const ulonglong2* k2p = (const ulonglong2*)&keys[sub * 128];
    #pragma unroll 16
    for (int j = 0; j < 64; j++) {
        ulonglong2 kk = k2p[j];
        part += (kk.x > mykey) + (kk.y > mykey);
    }
    pr[sub][el] = part;
    __syncthreads();
    if (tid < 128) {
        rankS[tid] = pr[0][tid] + pr[1][tid] + pr[2][tid] + pr[3][tid];
        scS[tid] = __uint_as_float((u32)(keys[qd * 128 + tid] >> 32));
    }
    __syncthreads();

    const int el2 = tid >> 2, q = tid & 3;
    const int rank = rankS[el2];
    if (rank < KSEL) {
        const float s = scS[el2];
        const float4* hr = (const float4*)&g_h[((size_t)b * NN + qd * 128 + el2) * DD + q * 16];
        float4* orow = (float4*)&out[((size_t)b * KSEL + rank) * DD + q * 16];
        #pragma unroll
        for (int c = 0; c < 4; c++) {
            float4 v = hr[c];
            orow[c] = make_float4(v.x * s, v.y * s, v.z * s, v.w * s);
        }
    }
}

// ---------------------------------------------------------------------------
extern "C" void kernel_launch(void* const* d_in, const int* in_sizes, int n_in,
                              void* d_out, int out_size)
{
    (void)in_sizes; (void)n_in; (void)out_size;
    const float* x      = (const float*)d_in[0];
    const float* attw   = (const float*)d_in[1];
    const float* attb   = (const float*)d_in[2];
    const float* attv   = (const float*)d_in[3];
    const float* pwa_w  = (const float*)d_in[4];
    const float* pwa_b  = (const float*)d_in[5];
    const float* pwo_w  = (const float*)d_in[6];
    const float* pwo_b  = (const float*)d_in[7];
    const float* gamma  = (const float*)d_in[8];
    const float* beta   = (const float*)d_in[9];
    const float* poolw  = (const float*)d_in[10];
    const float* poolb  = (const float*)d_in[11];

    cudaFuncSetAttribute(k1_logits, cudaFuncAttributeMaxDynamicSharedMemorySize, SMEM1);
    const int SMEM2 = (ITILE * NN + NN * DD + 3 * ITILE * DD + ITILE) * (int)sizeof(float);
    cudaFuncSetAttribute(k2_head, cudaFuncAttributeMaxDynamicSharedMemorySize, SMEM2);

    k0_cvt<<<BB * NN * 32 / 256, 256>>>(x);
    dim3 g1(NN / G, BB);
    k1_logits<<<g1, 256, SMEM1>>>(x, attw, attb, attv);
    dim3 g2(NN / ITILE, BB);
    k2_head<<<g2, 1024, SMEM2>>>(x, pwa_w, pwa_b, pwo_w, pwo_b, gamma, beta, poolw, poolb);
    dim3 g3(BB, 4);
    k3_topk<<<g3, 512>>>((float*)d_out);
}

// round 17
// speedup vs baseline: 1.0599x; 1.0599x over previous
#include <cuda_runtime.h>
#include <cuda_fp16.h>
#include <cstdint>
#include <math.h>

typedef unsigned long long ull;
typedef unsigned int u32;

#define NN 512
#define DD 64
#define BB 8
#define KSEL 256
#define G 4                   // i-values per CTA in k1

// Scratch (no allocation allowed)
__device__ float g_L[(size_t)BB * NN * NN];   // logits  8 MB
__device__ float g_h[(size_t)BB * NN * DD];   // h after selu
__device__ float g_s[(size_t)BB * NN];        // sigmoid scores
__device__ __half2 g_xhi[(size_t)BB * NN * 32];  // fp16 hi of x
__device__ __half2 g_xlo[(size_t)BB * NN * 32];  // fp16 lo residual

// Fast tanh: ex2.approx + rcp.approx + 1 Newton step. abs err ~1e-7.
__device__ __forceinline__ float fast_tanh(float x) {
    float ax = fabsf(x), t, r;
    asm("ex2.approx.f32 %0, %1;" : "=f"(t) : "f"(ax * -2.8853900817779268f));
    float u = 1.0f + t;
    asm("rcp.approx.f32 %0, %1;" : "=f"(r) : "f"(u));
    r = r * fmaf(-u, r, 2.0f);
    return copysignf((1.0f - t) * r, x);
}

__device__ __forceinline__ u32 smem_u32(const void* p) {
    u32 a;
    asm("{ .reg .u64 t; cvta.to.shared.u64 t, %1; cvt.u32.u64 %0, t; }" : "=r"(a) : "l"(p));
    return a;
}

#define LDSM4(r0, r1, r2, r3, a) \
    asm volatile("ldmatrix.sync.aligned.m8n8.x4.shared.b16 {%0,%1,%2,%3}, [%4];" \
        : "=r"(r0), "=r"(r1), "=r"(r2), "=r"(r3) : "r"(a))

__device__ __forceinline__ void mma16816(float* c, const u32* a, u32 b0, u32 b1) {
    asm volatile(
        "mma.sync.aligned.m16n8k16.row.col.f32.f16.f16.f32 "
        "{%0,%1,%2,%3}, {%4,%5,%6,%7}, {%8,%9}, {%0,%1,%2,%3};"
        : "+f"(c[0]), "+f"(c[1]), "+f"(c[2]), "+f"(c[3])
        : "r"(a[0]), "r"(a[1]), "r"(a[2]), "r"(a[3]), "r"(b0), "r"(b1));
}

// ---------------- Kernel 0: convert x to fp16 hi/lo (once) ----------------
__global__ __launch_bounds__(256) void k0_cvt(const float* __restrict__ x)
{
    int t = blockIdx.x * 256 + threadIdx.x;   // over 131072 float2
    float2 v = ((const float2*)x)[t];
    __half h0 = __float2half_rn(v.x), h1 = __float2half_rn(v.y);
    __half l0 = __float2half_rn(v.x - __half2float(h0));
    __half l1 = __float2half_rn(v.y - __half2float(h1));
    g_xhi[t] = __halves2half2(h0, h1);
    g_xlo[t] = __halves2half2(l0, l1);
}

// ---------------- Kernel 1: logits via HMMA fp16 hi/lo (R15 proven) --------
// Full-256-j CTAs, 32 j-rows per warp (2 m16 tiles), G=4 i per CTA.
// Swizzled 128B rows, single-buffer B, 2 syncs per g.
#define RWIN  260            // window rows: 256 + G
#define ATILE (RWIN * 128)   // 33280
#define BTILE (64 * 128)     // 8192
#define OFF_XI  0            // G*64 floats = 1024 B
#define OFF_VV  1024
#define OFF_BV  1280
#define OFF_RED 1536
#define OFF_AHI 2048
#define OFF_ALO (OFF_AHI + ATILE)
#define OFF_BHI (OFF_ALO + ATILE)
#define OFF_BLO (OFF_BHI + BTILE)
#define SMEM1   (OFF_BLO + BTILE)            // 84992 bytes -> 2 CTAs/SM

// swizzle: 16B chunk c (0..7) of row r stored at chunk (c ^ (r&7))
#define SWZ(r, c) ((u32)((r) * 128 + ((((c) ^ ((r) & 7))) << 4)))

__global__ __launch_bounds__(256, 2) void k1_logits(
    const float* __restrict__ x, const float* __restrict__ attw,
    const float* __restrict__ attb, const float* __restrict__ attv)
{
    extern __shared__ char smem[];
    const u32 sb = smem_u32(smem);
    const int tid = threadIdx.x, w = tid >> 5, lane = tid & 31;
    const int i0 = blockIdx.x * G, b = blockIdx.y;

    float* xia = (float*)(smem + OFF_XI);     // [G][64]
    float* vv  = (float*)(smem + OFF_VV);
    float* bv  = (float*)(smem + OFF_BV);
    float* red = (float*)(smem + OFF_RED);

    const float* xb = x + (size_t)b * NN * DD;

    if (tid < 64) { vv[tid] = attv[tid]; bv[tid] = attb[tid]; }
    xia[tid] = xb[(size_t)i0 * DD + tid];     // rows i0..i0+3 contiguous

    // A fill: fp16 hi/lo rows for j-offsets [0, 259], swizzled
    {
        const float4* xh4 = (const float4*)g_xhi;
        const float4* xl4 = (const float4*)g_xlo;
        for (int idx = tid; idx < RWIN * 8; idx += 256) {
            int r = idx >> 3, c = idx & 7;
            int grow = (i0 + r) & (NN - 1);
            size_t src = (size_t)(b * NN + grow) * 8 + c;
            u32 dst = SWZ(r, c);
            *(float4*)(smem + OFF_AHI + dst) = xh4[src];
            *(float4*)(smem + OFF_ALO + dst) = xl4[src];
        }
    }

    // B fill: B[o][d] = x_i[d]*W[d][o], fp16 hi/lo, swizzled, paired stores
    auto fillB = [&](int g) {
        char* bhi = smem + OFF_BHI;
        char* blo = smem + OFF_BLO;
        const float* xg = xia + g * 64;
        #pragma unroll
        for (int k = 0; k < 8; k++) {      // 64 o x 32 d-pairs / 256 threads
            int idx = tid + k * 256;
            int dp = idx >> 6, o = idx & 63;
            float w0 = xg[2 * dp]     * attw[(2 * dp)     * 64 + o];
            float w1 = xg[2 * dp + 1] * attw[(2 * dp + 1) * 64 + o];
            __half h0 = __float2half_rn(w0), h1 = __float2half_rn(w1);
            __half l0 = __float2half_rn(w0 - __half2float(h0));
            __half l1 = __float2half_rn(w1 - __half2float(h1));
            u32 off = SWZ(o, dp >> 2) + (u32)((dp & 3) * 4);
            *(__half2*)(bhi + off) = __halves2half2(h0, h1);
            *(__half2*)(blo + off) = __halves2half2(l0, l1);
        }
    };

    // lane decomposition for ldmatrix addressing
    const int la15 = lane & 15;
    const u32 la7  = (u32)(lane & 7);
    const u32 ak8  = (u32)((lane >> 4) & 1);   // A k-chunk select
    const u32 bk8  = (u32)((lane >> 3) & 1);   // B k-chunk select
    const u32 bhi8 = (u32)(((lane >> 4) & 1) * 8);

    for (int g = 0; g < G; g++) {
        const int i = i0 + g;
        __syncthreads();   // prologue (g=0) / prior-g B reads done
        fillB(g);
        __syncthreads();   // B visible

        const int rA = w * 32 + la15 + g;      // (rA+16)&7 == rA&7
        const u32 r7a = (u32)(rA & 7);
        const u32 aHiRow = sb + OFF_AHI + (u32)(rA * 128);
        const u32 aLoRow = aHiRow + ATILE;
        const u32 bB = sb + OFF_BHI;

        float acc[2][8][4];
        #pragma unroll
        for (int mt = 0; mt < 2; mt++)
            #pragma unroll
            for (int nt = 0; nt < 8; nt++)
                #pragma unroll
                for (int q = 0; q < 4; q++) acc[mt][nt][q] = 0.f;

        #pragma unroll
        for (int ks = 0; ks < 4; ks++) {
            const u32 aswz = (u32)((((u32)(2 * ks) + ak8) ^ r7a) << 4);
            const u32 bswz = (u32)((((u32)(2 * ks) + bk8) ^ la7) << 4);
            u32 ah[2][4], bh[8][2];
            LDSM4(ah[0][0], ah[0][1], ah[0][2], ah[0][3], aHiRow + aswz);
            LDSM4(ah[1][0], ah[1][1], ah[1][2], ah[1][3], aHiRow + 16 * 128 + aswz);
            #pragma unroll
            for (int q = 0; q < 4; q++) {
                u32 brow = bB + (u32)((q * 16 + bhi8 + la7) * 128) + bswz;
                LDSM4(bh[2 * q][0], bh[2 * q][1], bh[2 * q + 1][0], bh[2 * q + 1][1], brow);
            }
            #pragma unroll
            for (int mt = 0; mt < 2; mt++)
                #pragma unroll
                for (int nt = 0; nt < 8; nt++)
                    mma16816(acc[mt][nt], ah[mt], bh[nt][0], bh[nt][1]);
            {
                u32 bl[8][2];
                #pragma unroll
                for (int q = 0; q < 4; q++) {
                    u32 brow = bB + BTILE + (u32)((q * 16 + bhi8 + la7) * 128) + bswz;
                    LDSM4(bl[2 * q][0], bl[2 * q][1], bl[2 * q + 1][0], bl[2 * q + 1][1], brow);
                }
                #pragma unroll
                for (int mt = 0; mt < 2; mt++)
                    #pragma unroll
                    for (int nt = 0; nt < 8; nt++)
                        mma16816(acc[mt][nt], ah[mt], bl[nt][0], bl[nt][1]);
            }
            {
                u32 al[2][4];
                LDSM4(al[0][0], al[0][1], al[0][2], al[0][3], aLoRow + aswz);
                LDSM4(al[1][0], al[1][1], al[1][2], al[1][3], aLoRow + 16 * 128 + aswz);
                #pragma unroll
                for (int mt = 0; mt < 2; mt++)
                    #pragma unroll
                    for (int nt = 0; nt < 8; nt++)
                        mma16816(acc[mt][nt], al[mt], bh[nt][0], bh[nt][1]);
            }
        }

        // Epilogue: tanh + v-weighted o-reduction; lanes share j across c=lane&3
        {
            const int gq = lane >> 2, c = lane & 3;
            float2 vv2[8], bv2[8];
            #pragma unroll
            for (int nt = 0; nt < 8; nt++) {
                vv2[nt] = *(const float2*)&vv[nt * 8 + 2 * c];
                bv2[nt] = *(const float2*)&bv[nt * 8 + 2 * c];
            }
            #pragma unroll
            for (int mt = 0; mt < 2; mt++) {
                #pragma unroll
                for (int rh = 0; rh < 2; rh++) {
                    float s = 0.f;
                    #pragma unroll
                    for (int nt = 0; nt < 8; nt++) {
                        s += vv2[nt].x * fast_tanh(acc[mt][nt][2 * rh]     + bv2[nt].x);
                        s += vv2[nt].y * fast_tanh(acc[mt][nt][2 * rh + 1] + bv2[nt].y);
                    }
                    s += __shfl_xor_sync(~0u, s, 1);
                    s += __shfl_xor_sync(~0u, s, 2);
                    if (c == 0) {
                        int jloc = w * 32 + mt * 16 + rh * 8 + gq;
                        int jg = (i + jloc) & (NN - 1);
                        g_L[((size_t)b * NN + i) * NN + jg] = s;
                        g_L[((size_t)b * NN + jg) * NN + i] = s;  // mirror
                    }
                }
            }
        }
    }

    // Tail k=256: CTAs with i0<256; all G i's at once
    if (i0 < 256) {
        __syncthreads();
        const int g = tid >> 6, o = tid & 63;
        const float* xg = xia + g * 64;
        const float* xj = xb + (size_t)(i0 + g + 256) * DD;
        float q2 = bv[o];
        #pragma unroll 8
        for (int d = 0; d < 64; d++)
            q2 = fmaf(xg[d] * attw[d * 64 + o], xj[d], q2);
        float s = vv[o] * fast_tanh(q2);
        #pragma unroll
        for (int off = 16; off; off >>= 1) s += __shfl_xor_sync(~0u, s, off);
        if (lane == 0) red[w] = s;       // warp w covers (g = w>>1, o-half = w&1)
        __syncthreads();
        if (tid < G) {
            float sv = red[2 * tid] + red[2 * tid + 1];
            int ii = i0 + tid, jg = ii + 256;
            g_L[((size_t)b * NN + ii) * NN + jg] = sv;
            g_L[((size_t)b * NN + jg) * NN + ii] = sv;
        }
    }
}

// ---------------------------------------------------------------------------
// Kernel 2 (tiled, 1024 threads): j-split agg halves the per-CTA critical path.
// ---------------------------------------------------------------------------
#define ITILE 32
__global__ __launch_bounds__(1024, 1) void k2_head(
    const float* __restrict__ x,
    const float* __restrict__ pwa_w, const float* __restrict__ pwa_b,
    const float* __restrict__ pwo_w, const float* __restrict__ pwo_b,
    const float* __restrict__ gamma, const float* __restrict__ beta,
    const float* __restrict__ poolw, const float* __restrict__ poolb)
{
    extern __shared__ float s2[];
    float* att  = s2;                        // [32][512] (reused as hsm later)
    float* xs   = s2 + ITILE * NN;           // [512][64]
    float* agg  = xs + NN * DD;              // [32][64]
    float* aggp = agg + ITILE * DD;          // [2][32][64]
    float* inv  = aggp + 2 * ITILE * DD;     // [32]
    float* hsm  = att;

    const int itile = blockIdx.x, b = blockIdx.y;
    const int tid = threadIdx.x;
    const int wid = tid >> 5, lane = tid & 31;

    {
        const float4* Ls = (const float4*)(g_L + ((size_t)b * NN + itile * ITILE) * NN);
        float4* Ld = (float4*)att;
        for (int idx = tid; idx < ITILE * NN / 4; idx += 1024) Ld[idx] = Ls[idx];
        const float4* Xs = (const float4*)(x + (size_t)b * NN * DD);
        float4* Xd = (float4*)xs;
        for (int idx = tid; idx < NN * DD / 4; idx += 1024) Xd[idx] = Xs[idx];
    }
    __syncthreads();

    // Row softmax: 32 warps, 1 row each; exp in place (unnormalized), 1/sum
    {
        int r = wid;
        float* row = att + r * NN;
        float m = -1e30f;
        #pragma unroll 4
        for (int j = lane; j < NN; j += 32) m = fmaxf(m, row[j]);
        #pragma unroll
        for (int off = 16; off; off >>= 1) m = fmaxf(m, __shfl_xor_sync(~0u, m, off));
        float ssum = 0.f;
        #pragma unroll 4
        for (int j = lane; j < NN; j += 32) {
            float e = __expf(row[j] - m);
            row[j] = e;
            ssum += e;
        }
        #pragma unroll
        for (int off = 16; off; off >>= 1) ssum += __shfl_xor_sync(~0u, ssum, off);
        if (lane == 0) inv[r] = 1.0f / ssum;
    }
    __syncthreads();

    // agg partials: (seg, ig, d): rows ig*4..+3, j in [seg*256, seg*256+256)
    {
        const int d = tid & 63, ig = (tid >> 6) & 7, seg = tid >> 9;
        float acc[4] = {0, 0, 0, 0};
        for (int j = seg * 256; j < seg * 256 + 256; j += 4) {
            float x0 = xs[(j + 0) * DD + d];
            float x1 = xs[(j + 1) * DD + d];
            float x2 = xs[(j + 2) * DD + d];
            float x3 = xs[(j + 3) * DD + d];
            #pragma unroll
            for (int s = 0; s < 4; s++) {
                float4 a = *(const float4*)&att[(ig * 4 + s) * NN + j];
                acc[s] = fmaf(a.x, x0, acc[s]);
                acc[s] = fmaf(a.y, x1, acc[s]);
                acc[s] = fmaf(a.z, x2, acc[s]);
                acc[s] = fmaf(a.w, x3, acc[s]);
            }
        }
        #pragma unroll
        for (int s = 0; s < 4; s++)
            aggp[(seg * ITILE + ig * 4 + s) * DD + d] = acc[s];
    }
    __syncthreads();
    for (int t = tid; t < ITILE * DD; t += 1024)
        agg[t] = (aggp[t] + aggp[ITILE * DD + t]) * inv[t >> 6];
    __syncthreads();

    // h = agg@pwa + x_i@pwo + biases, BN(eval) scale, selu; 2 rows/thread
    {
        const int o = tid & 63, ig2 = tid >> 6;   // ig2 in 0..15
        float hv[2];
        float pb = pwa_b[o] + pwo_b[o];
        hv[0] = pb; hv[1] = pb;
        #pragma unroll 8
        for (int dd = 0; dd < 64; dd++) {
            float wa = __ldg(&pwa_w[dd * 64 + o]);
            float wo = __ldg(&pwo_w[dd * 64 + o]);
            #pragma unroll
            for (int s = 0; s < 2; s++) {
                int ii = ig2 * 2 + s;
                hv[s] = fmaf(agg[ii * DD + dd], wa, hv[s]);
                hv[s] = fmaf(xs[(itile * ITILE + ii) * DD + dd], wo, hv[s]);
            }
        }
        const float BNS = 0.99999500003749969f;
        float gam = gamma[o] * BNS, bet = beta[o];
        const float SC = 1.0507009873554804934193349852946f;
        const float AL = 1.6732632423543772848170429916717f;
        #pragma unroll
        for (int s = 0; s < 2; s++) {
            float h = fmaf(hv[s], gam, bet);
            h = h > 0.f ? SC * h : SC * AL * expm1f(h);
            hsm[(ig2 * 2 + s) * DD + o] = h;
        }
    }
    __syncthreads();

    if (tid < ITILE) {
        float z = poolb[0];
        #pragma unroll 8
        for (int oo = 0; oo < 64; oo++) z = fmaf(hsm[tid * 64 + oo], poolw[oo], z);
        g_s[(size_t)b * NN + itile * ITILE + tid] = 1.0f / (1.0f + expf(-z));
    }
    {
        float4* gh = (float4*)(g_h + ((size_t)b * NN + itile * ITILE) * DD);
        const float4* hs = (const float4*)hsm;
        for (int idx = tid; idx < ITILE * DD / 4; idx += 1024) gh[idx] = hs[idx];
    }
}

// ---------------------------------------------------------------------------
// Kernel 3: split-scan rank top-256 (unchanged proven version).
// ---------------------------------------------------------------------------
__global__ __launch_bounds__(512) void k3_topk(float* __restrict__ out)
{
    __shared__ ull keys[NN];
    __shared__ int pr[4][128];
    __shared__ int rankS[128];
    __shared__ float scS[128];
    const int b = blockIdx.x, qd = blockIdx.y, tid = threadIdx.x;

    {
        float sc = g_s[(size_t)b * NN + tid];
        keys[tid] = ((ull)__float_as_uint(sc) << 32) | (ull)(unsigned)(511 - tid);
    }
    __syncthreads();

    const int sub = tid >> 7, el = tid & 127;
    const int e = qd * 128 + el;
    const ull mykey = keys[e];
    int part = 0;
    const ulonglong2* k2p = (const ulonglong2*)&keys[sub * 128];
    #pragma unroll 16
    for (int j = 0; j < 64; j++) {
        ulonglong2 kk = k2p[j];
        part += (kk.x > mykey) + (kk.y > mykey);
    }
    pr[sub][el] = part;
    __syncthreads();
    if (tid < 128) {
        rankS[tid] = pr[0][tid] + pr[1][tid] + pr[2][tid] + pr[3][tid];
        scS[tid] = __uint_as_float((u32)(keys[qd * 128 + tid] >> 32));
    }
    __syncthreads();

    const int el2 = tid >> 2, q = tid & 3;
    const int rank = rankS[el2];
    if (rank < KSEL) {
        const float s = scS[el2];
        const float4* hr = (const float4*)&g_h[((size_t)b * NN + qd * 128 + el2) * DD + q * 16];
        float4* orow = (float4*)&out[((size_t)b * KSEL + rank) * DD + q * 16];
        #pragma unroll
        for (int c = 0; c < 4; c++) {
            float4 v = hr[c];
            orow[c] = make_float4(v.x * s, v.y * s, v.z * s, v.w * s);
        }
    }
}

// ---------------------------------------------------------------------------
extern "C" void kernel_launch(void* const* d_in, const int* in_sizes, int n_in,
                              void* d_out, int out_size)
{
    (void)in_sizes; (void)n_in; (void)out_size;
    const float* x      = (const float*)d_in[0];
    const float* attw   = (const float*)d_in[1];
    const float* attb   = (const float*)d_in[2];
    const float* attv   = (const float*)d_in[3];
    const float* pwa_w  = (const float*)d_in[4];
    const float* pwa_b  = (const float*)d_in[5];
    const float* pwo_w  = (const float*)d_in[6];
    const float* pwo_b  = (const float*)d_in[7];
    const float* gamma  = (const float*)d_in[8];
    const float* beta   = (const float*)d_in[9];
    const float* poolw  = (const float*)d_in[10];
    const float* poolb  = (const float*)d_in[11];

    cudaFuncSetAttribute(k1_logits, cudaFuncAttributeMaxDynamicSharedMemorySize, SMEM1);
    const int SMEM2 = (ITILE * NN + NN * DD + 3 * ITILE * DD + ITILE) * (int)sizeof(float);
    cudaFuncSetAttribute(k2_head, cudaFuncAttributeMaxDynamicSharedMemorySize, SMEM2);

    k0_cvt<<<BB * NN * 32 / 256, 256>>>(x);
    dim3 g1(NN / G, BB);
    k1_logits<<<g1, 256, SMEM1>>>(x, attw, attb, attv);
    dim3 g2(NN / ITILE, BB);
    k2_head<<<g2, 1024, SMEM2>>>(x, pwa_w, pwa_b, pwo_w, pwo_b, gamma, beta, poolw, poolb);
    dim3 g3(BB, 4);
    k3_topk<<<g3, 512>>>((float*)d_out);
}